// round 12
// baseline (speedup 1.0000x reference)
#include <cuda_runtime.h>
#include <cuda_fp16.h>
#include <cstdint>

#define NN 8192
#define EE 262144
#define DD 256
#define UMAX (EE + NN)
#define SLOT 128
#define BN_EPS 1e-5f

// GEMM tiling
#define BM 128
#define BNT 64
#define BK 32
#define ASH 40   // half-A smem stride (halves)
#define ASF 36   // float-A smem stride (floats)

// ---------------- device scratch ----------------
__device__ unsigned g_bitmap[NN * (NN / 32)];
__device__ int      g_deg[NN];
__device__ int      g_nz;
__device__ int      g_colidx[NN * SLOT];
__device__ float    g_dinv[NN];
__device__ __half   g_Xh[NN * DD];
__device__ __half   g_Wh[3][DD * DD];
__device__ __half   g_Zh[NN * DD];     // GEMM output (fp16)
__device__ float    g_Abuf[NN * DD];   // agg output (fp32, pre-BN)
__device__ float    g_sum[3][DD];
__device__ float    g_sumsq[3][DD];

// ---------------- preprocessing ----------------
__global__ void detect_k(const unsigned* __restrict__ e) {
    int i = blockIdx.x * blockDim.x + threadIdx.x;
    if (i < 4096 && e[2 * i + 1] != 0u) atomicOr(&g_nz, 1);
}

__global__ void dedup_k(const void* __restrict__ eptr) {
    int i = blockIdx.x * blockDim.x + threadIdx.x;
    if (i >= UMAX) return;
    int is64 = (g_nz == 0);
    int r, c;
    if (i < EE) {
        if (is64) {
            const long long* e = (const long long*)eptr;
            r = (int)e[i];
            c = (int)e[EE + i];
        } else {
            const int* e = (const int*)eptr;
            r = e[i];
            c = e[EE + i];
        }
    } else {
        r = c = i - EE;   // self loop
    }
    unsigned bit = (unsigned)r * NN + (unsigned)c;
    unsigned mask = 1u << (bit & 31u);
    unsigned old = atomicOr(&g_bitmap[bit >> 5], mask);
    if (!(old & mask)) {
        int slot = atomicAdd(&g_deg[r], 1);
        if (slot < SLOT) g_colidx[r * SLOT + slot] = c;
    }
}

__global__ void dinv_k() {
    int i = blockIdx.x * blockDim.x + threadIdx.x;
    if (i < NN) g_dinv[i] = rsqrtf((float)g_deg[i]);
}

// ---------------- fp32 -> fp16 elementwise ----------------
__device__ __forceinline__ uint2 cvt4(float4 v) {
    __half2 lo = __floats2half2_rn(v.x, v.y);
    __half2 hi = __floats2half2_rn(v.z, v.w);
    uint2 u;
    u.x = *reinterpret_cast<unsigned*>(&lo);
    u.y = *reinterpret_cast<unsigned*>(&hi);
    return u;
}

__global__ void f2h_k(const float4* __restrict__ in, uint2* __restrict__ out, int n4) {
    int i = blockIdx.x * blockDim.x + threadIdx.x;
    if (i < n4) out[i] = cvt4(in[i]);
}

__global__ void f2hx2_k(const float4* __restrict__ a, uint2* __restrict__ oa, int n4a,
                        const float4* __restrict__ b, uint2* __restrict__ ob, int n4b) {
    int i = blockIdx.x * blockDim.x + threadIdx.x;
    if (i < n4a) {
        oa[i] = cvt4(a[i]);
    } else {
        int j = i - n4a;
        if (j < n4b) ob[j] = cvt4(b[j]);
    }
}

// ---------------- GEMM (fp16 HMMA m16n8k16, cp.async double-buffer) ----------
// FUSE=0: A is fp16, used as-is (layer 1).
// FUSE=1: A is fp32 un-normalized; BN+ReLU applied in fp32 on the frag path,
//         quantization to fp16 happens POST-normalization (error-safe).
__device__ __forceinline__ void cpa16(void* dst, const void* src) {
    unsigned d = (unsigned)__cvta_generic_to_shared(dst);
    asm volatile("cp.async.ca.shared.global [%0], [%1], 16;\n" :: "r"(d), "l"(src));
}

template <int FUSE>
__global__ __launch_bounds__(256, 2) void gemm_k(
    const void* __restrict__ Ain, const __half* __restrict__ W,
    const float* __restrict__ bias, __half* __restrict__ Z, int fuse_layer,
    const float* __restrict__ gamma, const float* __restrict__ beta)
{
    extern __shared__ char smraw[];
    // layout: [A stages][B stages][ssc][ssh]
    float*  Af = (float*)smraw;                                   // FUSE=1
    __half* Ah = (__half*)smraw;                                  // FUSE=0
    __half* Bs = (__half*)(smraw + (FUSE ? 2 * BM * ASF * 4 : 2 * BM * ASH * 2));
    float*  ssc = (float*)((char*)Bs + 2 * BNT * ASH * 2);
    float*  ssh = ssc + DD;
#define ASH_(s,r,c) Ah[((s) * BM  + (r)) * ASH + (c)]
#define ASF_(s,r,c) Af[((s) * BM  + (r)) * ASF + (c)]
#define BS_(s,r,c)  Bs[((s) * BNT + (r)) * ASH + (c)]

    int tid = threadIdx.x;
    if (FUSE) {
        float mu = g_sum[fuse_layer][tid] * (1.f / NN);
        float var = g_sumsq[fuse_layer][tid] * (1.f / NN) - mu * mu;
        float rs = rsqrtf(var + BN_EPS);
        float sc = gamma[tid] * rs;
        ssc[tid] = sc;
        ssh[tid] = beta[tid] - mu * sc;
    }

    int bm = blockIdx.x * BM, bn = blockIdx.y * BNT;
    int wid = tid >> 5, lane = tid & 31;
    int g = lane >> 2, t = lane & 3;
    int wm = wid & 3, wn = wid >> 2;       // 4 x 2 warps, 32x32 per warp

    const __half* AbaseH = (const __half*)Ain + (size_t)bm * DD;
    const float*  AbaseF = (const float*)Ain + (size_t)bm * DD;
    const __half* Wbase = W + (size_t)bn * DD;

    float acc[2][4][4];
    #pragma unroll
    for (int mt = 0; mt < 2; mt++)
        #pragma unroll
        for (int nt = 0; nt < 4; nt++)
            #pragma unroll
            for (int q = 0; q < 4; q++) acc[mt][nt][q] = 0.f;

    // ---- fill helpers (per stage)
    auto fill_stage = [&](int st, int kofs) {
        if (FUSE) {
            // A: 128x32 floats = 1024 x 16B chunks, 4 per thread
            #pragma unroll
            for (int it = 0; it < 4; it++) {
                int f = tid + it * 256;
                int r = f >> 3, c4 = (f & 7) * 4;
                cpa16(&ASF_(st, r, c4), AbaseF + r * DD + kofs + c4);
            }
        } else {
            // A: 128x32 halves = 512 x 16B chunks, 2 per thread
            #pragma unroll
            for (int it = 0; it < 2; it++) {
                int f = tid + it * 256;
                int r = f >> 2, ch = (f & 3) * 8;
                cpa16(&ASH_(st, r, ch), AbaseH + r * DD + kofs + ch);
            }
        }
        // B: 64x32 halves = 256 x 16B chunks, 1 per thread
        {
            int r = tid >> 2, ch = (tid & 3) * 8;
            cpa16(&BS_(st, r, ch), Wbase + r * DD + kofs + ch);
        }
        asm volatile("cp.async.commit_group;");
    };

    fill_stage(0, 0);
    __syncthreads();   // publishes ssc/ssh too

    #pragma unroll 2
    for (int kb = 0; kb < DD / BK; kb++) {
        int s = kb & 1;
        int kglob = kb * BK;
        if (kb < DD / BK - 1) {
            fill_stage(s ^ 1, kglob + BK);
            asm volatile("cp.async.wait_group 1;");
        } else {
            asm volatile("cp.async.wait_group 0;");
        }
        __syncthreads();

        #pragma unroll
        for (int ks = 0; ks < 2; ks++) {
            int k16 = ks * 16;
            unsigned af[2][4], bf[4][2];
            if (FUSE) {
                int kc = kglob + k16 + 2 * t;
                float scA0 = ssc[kc],     shA0 = ssh[kc];
                float scA1 = ssc[kc + 1], shA1 = ssh[kc + 1];
                float scB0 = ssc[kc + 8], shB0 = ssh[kc + 8];
                float scB1 = ssc[kc + 9], shB1 = ssh[kc + 9];
                #pragma unroll
                for (int mt = 0; mt < 2; mt++) {
                    int rb = wm * 32 + mt * 16;
                    float2 v0 = *(const float2*)&ASF_(s, rb + g,     k16 + 2 * t);
                    float2 v1 = *(const float2*)&ASF_(s, rb + g + 8, k16 + 2 * t);
                    float2 v2 = *(const float2*)&ASF_(s, rb + g,     k16 + 2 * t + 8);
                    float2 v3 = *(const float2*)&ASF_(s, rb + g + 8, k16 + 2 * t + 8);
                    __half2 h0 = __floats2half2_rn(
                        fmaxf(fmaf(v0.x, scA0, shA0), 0.f),
                        fmaxf(fmaf(v0.y, scA1, shA1), 0.f));
                    __half2 h1 = __floats2half2_rn(
                        fmaxf(fmaf(v1.x, scA0, shA0), 0.f),
                        fmaxf(fmaf(v1.y, scA1, shA1), 0.f));
                    __half2 h2 = __floats2half2_rn(
                        fmaxf(fmaf(v2.x, scB0, shB0), 0.f),
                        fmaxf(fmaf(v2.y, scB1, shB1), 0.f));
                    __half2 h3 = __floats2half2_rn(
                        fmaxf(fmaf(v3.x, scB0, shB0), 0.f),
                        fmaxf(fmaf(v3.y, scB1, shB1), 0.f));
                    af[mt][0] = *reinterpret_cast<unsigned*>(&h0);
                    af[mt][1] = *reinterpret_cast<unsigned*>(&h1);
                    af[mt][2] = *reinterpret_cast<unsigned*>(&h2);
                    af[mt][3] = *reinterpret_cast<unsigned*>(&h3);
                }
            } else {
                #pragma unroll
                for (int mt = 0; mt < 2; mt++) {
                    int rb = wm * 32 + mt * 16;
                    af[mt][0] = *(const unsigned*)&ASH_(s, rb + g,     k16 + 2 * t);
                    af[mt][1] = *(const unsigned*)&ASH_(s, rb + g + 8, k16 + 2 * t);
                    af[mt][2] = *(const unsigned*)&ASH_(s, rb + g,     k16 + 2 * t + 8);
                    af[mt][3] = *(const unsigned*)&ASH_(s, rb + g + 8, k16 + 2 * t + 8);
                }
            }
            #pragma unroll
            for (int nt = 0; nt < 4; nt++) {
                int nb = wn * 32 + nt * 8;
                bf[nt][0] = *(const unsigned*)&BS_(s, nb + g, k16 + 2 * t);
                bf[nt][1] = *(const unsigned*)&BS_(s, nb + g, k16 + 2 * t + 8);
            }
            #pragma unroll
            for (int mt = 0; mt < 2; mt++)
                #pragma unroll
                for (int nt = 0; nt < 4; nt++) {
                    asm volatile(
                        "mma.sync.aligned.m16n8k16.row.col.f32.f16.f16.f32 "
                        "{%0,%1,%2,%3},{%4,%5,%6,%7},{%8,%9},{%0,%1,%2,%3};"
                        : "+f"(acc[mt][nt][0]), "+f"(acc[mt][nt][1]),
                          "+f"(acc[mt][nt][2]), "+f"(acc[mt][nt][3])
                        : "r"(af[mt][0]), "r"(af[mt][1]), "r"(af[mt][2]), "r"(af[mt][3]),
                          "r"(bf[nt][0]), "r"(bf[nt][1]));
                }
        }
        __syncthreads();
    }

    #pragma unroll
    for (int mt = 0; mt < 2; mt++)
        #pragma unroll
        for (int nt = 0; nt < 4; nt++) {
            int r0 = bm + wm * 32 + mt * 16 + g;
            int col = bn + wn * 32 + nt * 8 + 2 * t;
            float b0 = bias[col], b1 = bias[col + 1];
            __half2 p0 = __floats2half2_rn(acc[mt][nt][0] + b0, acc[mt][nt][1] + b1);
            __half2 p1 = __floats2half2_rn(acc[mt][nt][2] + b0, acc[mt][nt][3] + b1);
            *reinterpret_cast<__half2*>(Z + (size_t)r0 * DD + col)       = p0;
            *reinterpret_cast<__half2*>(Z + (size_t)(r0 + 8) * DD + col) = p1;
        }
#undef ASH_
#undef ASF_
#undef BS_
}

// ---------------- sparse aggregation (fp16 Z -> fp32 Out) + fused BN stats ----
__global__ __launch_bounds__(256) void agg_k(const __half* __restrict__ Z,
                                             float* __restrict__ Out, int layer) {
    __shared__ float sv[8][DD];
    int tid = threadIdx.x;
    int w = tid >> 5;
    int row = blockIdx.x * 8 + w;
    int lane = tid & 31;

    int deg = g_deg[row];
    const int* cols = &g_colidx[row * SLOT];
    float a[8];
    #pragma unroll
    for (int j = 0; j < 8; j++) a[j] = 0.f;

    int p = 0;
    for (; p + 4 <= deg; p += 4) {
        int cc[4];
        #pragma unroll
        for (int q = 0; q < 4; q++) cc[q] = cols[p + q];
        float dv[4];
        uint4 u[4];
        #pragma unroll
        for (int q = 0; q < 4; q++) {
            dv[q] = g_dinv[cc[q]];
            u[q] = __ldg((const uint4*)(Z + (size_t)cc[q] * DD) + lane);
        }
        #pragma unroll
        for (int q = 0; q < 4; q++) {
            float2 f0 = __half22float2(*reinterpret_cast<__half2*>(&u[q].x));
            float2 f1 = __half22float2(*reinterpret_cast<__half2*>(&u[q].y));
            float2 f2 = __half22float2(*reinterpret_cast<__half2*>(&u[q].z));
            float2 f3 = __half22float2(*reinterpret_cast<__half2*>(&u[q].w));
            a[0] = fmaf(dv[q], f0.x, a[0]); a[1] = fmaf(dv[q], f0.y, a[1]);
            a[2] = fmaf(dv[q], f1.x, a[2]); a[3] = fmaf(dv[q], f1.y, a[3]);
            a[4] = fmaf(dv[q], f2.x, a[4]); a[5] = fmaf(dv[q], f2.y, a[5]);
            a[6] = fmaf(dv[q], f3.x, a[6]); a[7] = fmaf(dv[q], f3.y, a[7]);
        }
    }
    for (; p < deg; p++) {
        int c = cols[p];
        float dv = g_dinv[c];
        uint4 u = __ldg((const uint4*)(Z + (size_t)c * DD) + lane);
        float2 f0 = __half22float2(*reinterpret_cast<__half2*>(&u.x));
        float2 f1 = __half22float2(*reinterpret_cast<__half2*>(&u.y));
        float2 f2 = __half22float2(*reinterpret_cast<__half2*>(&u.z));
        float2 f3 = __half22float2(*reinterpret_cast<__half2*>(&u.w));
        a[0] = fmaf(dv, f0.x, a[0]); a[1] = fmaf(dv, f0.y, a[1]);
        a[2] = fmaf(dv, f1.x, a[2]); a[3] = fmaf(dv, f1.y, a[3]);
        a[4] = fmaf(dv, f2.x, a[4]); a[5] = fmaf(dv, f2.y, a[5]);
        a[6] = fmaf(dv, f3.x, a[6]); a[7] = fmaf(dv, f3.y, a[7]);
    }
    float dr = g_dinv[row];
    #pragma unroll
    for (int j = 0; j < 8; j++) a[j] *= dr;

    float4* orow = reinterpret_cast<float4*>(Out + (size_t)row * DD);
    orow[lane * 2]     = make_float4(a[0], a[1], a[2], a[3]);
    orow[lane * 2 + 1] = make_float4(a[4], a[5], a[6], a[7]);

    #pragma unroll
    for (int j = 0; j < 8; j++) sv[w][lane * 8 + j] = a[j];
    __syncthreads();
    float s = 0.f, ss = 0.f;
    #pragma unroll
    for (int r = 0; r < 8; r++) {
        float v = sv[r][tid];
        s += v;
        ss = fmaf(v, v, ss);
    }
    atomicAdd(&g_sum[layer][tid], s);
    atomicAdd(&g_sumsq[layer][tid], ss);
}

// final BN apply (fp32 in/out, no relu)
__global__ __launch_bounds__(256) void apply_k(const float* __restrict__ A,
                                               float* __restrict__ out,
                                               const float* __restrict__ gamma,
                                               const float* __restrict__ beta) {
    __shared__ float ssc[DD], ssh[DD];
    int tid = threadIdx.x;
    {
        float mu = g_sum[2][tid] * (1.f / NN);
        float var = g_sumsq[2][tid] * (1.f / NN) - mu * mu;
        float rs = rsqrtf(var + BN_EPS);
        float sc = gamma[tid] * rs;
        ssc[tid] = sc;
        ssh[tid] = beta[tid] - mu * sc;
    }
    __syncthreads();
    int i = blockIdx.x * 256 + tid;
    int col = (i * 4) & (DD - 1);
    float4 v = reinterpret_cast<const float4*>(A)[i];
    float4 o;
    o.x = fmaf(v.x, ssc[col],     ssh[col]);
    o.y = fmaf(v.y, ssc[col + 1], ssh[col + 1]);
    o.z = fmaf(v.z, ssc[col + 2], ssh[col + 2]);
    o.w = fmaf(v.w, ssc[col + 3], ssh[col + 3]);
    reinterpret_cast<float4*>(out)[i] = o;
}

// ---------------- launch ----------------
extern "C" void kernel_launch(void* const* d_in, const int* in_sizes, int n_in,
                              void* d_out, int out_size) {
    const float* x   = (const float*)d_in[0];
    const void*  ei  = d_in[1];
    const float* W1  = (const float*)d_in[2];
    const float* b1  = (const float*)d_in[3];
    const float* W2  = (const float*)d_in[4];
    const float* b2  = (const float*)d_in[5];
    const float* W3  = (const float*)d_in[6];
    const float* b3  = (const float*)d_in[7];
    const float* g1  = (const float*)d_in[8];
    const float* be1 = (const float*)d_in[9];
    const float* g2  = (const float*)d_in[10];
    const float* be2 = (const float*)d_in[11];
    const float* g3  = (const float*)d_in[12];
    const float* be3 = (const float*)d_in[13];
    float* out = (float*)d_out;

    void *pZ, *pA, *pBm, *pDeg, *pSum, *pSq, *pNz, *pXh, *pWh;
    cudaGetSymbolAddress(&pZ, g_Zh);
    cudaGetSymbolAddress(&pA, g_Abuf);
    cudaGetSymbolAddress(&pBm, g_bitmap);
    cudaGetSymbolAddress(&pDeg, g_deg);
    cudaGetSymbolAddress(&pSum, g_sum);
    cudaGetSymbolAddress(&pSq, g_sumsq);
    cudaGetSymbolAddress(&pNz, g_nz);
    cudaGetSymbolAddress(&pXh, g_Xh);
    cudaGetSymbolAddress(&pWh, g_Wh);
    __half* Zh = (__half*)pZ;
    float*  Ab = (float*)pA;
    __half* Xh = (__half*)pXh;
    __half* Wh = (__half*)pWh;

    const int SMEM_H = 2 * BM * ASH * 2 + 2 * BNT * ASH * 2 + 2 * DD * 4;  // fp16 A
    const int SMEM_F = 2 * BM * ASF * 4 + 2 * BNT * ASH * 2 + 2 * DD * 4;  // fp32 A
    cudaFuncSetAttribute(gemm_k<0>, cudaFuncAttributeMaxDynamicSharedMemorySize, SMEM_H);
    cudaFuncSetAttribute(gemm_k<1>, cudaFuncAttributeMaxDynamicSharedMemorySize, SMEM_F);

    static cudaStream_t s_pre = nullptr;
    static cudaEvent_t ev_fork = nullptr, ev_join = nullptr;
    if (s_pre == nullptr) {
        cudaStreamCreateWithFlags(&s_pre, cudaStreamNonBlocking);
        cudaEventCreateWithFlags(&ev_fork, cudaEventDisableTiming);
        cudaEventCreateWithFlags(&ev_join, cudaEventDisableTiming);
    }

    cudaMemsetAsync(pSum, 0, sizeof(float) * 3 * DD);
    cudaMemsetAsync(pSq, 0, sizeof(float) * 3 * DD);

    // ---- fork: preprocessing + W2/W3 converts, concurrent with x/W1 + gemm1
    cudaEventRecord(ev_fork, 0);
    cudaStreamWaitEvent(s_pre, ev_fork, 0);
    cudaMemsetAsync(pBm, 0, sizeof(unsigned) * NN * (NN / 32), s_pre);
    cudaMemsetAsync(pDeg, 0, sizeof(int) * NN, s_pre);
    cudaMemsetAsync(pNz, 0, sizeof(int), s_pre);
    detect_k<<<16, 256, 0, s_pre>>>((const unsigned*)ei);
    dedup_k<<<(UMAX + 255) / 256, 256, 0, s_pre>>>(ei);
    dinv_k<<<NN / 256, 256, 0, s_pre>>>();
    f2h_k<<<(DD * DD / 4 + 255) / 256, 256, 0, s_pre>>>(
        (const float4*)W2, (uint2*)(Wh + 1 * DD * DD), DD * DD / 4);
    f2h_k<<<(DD * DD / 4 + 255) / 256, 256, 0, s_pre>>>(
        (const float4*)W3, (uint2*)(Wh + 2 * DD * DD), DD * DD / 4);
    cudaEventRecord(ev_join, s_pre);

    // main: x + W1 convert (single launch)
    f2hx2_k<<<(NN * DD / 4 + DD * DD / 4 + 255) / 256, 256>>>(
        (const float4*)x, (uint2*)Xh, NN * DD / 4,
        (const float4*)W1, (uint2*)(Wh + 0 * DD * DD), DD * DD / 4);

    dim3 ggrid(NN / BM, DD / BNT);

    // layer 1 — concurrent with preprocessing fork
    gemm_k<0><<<ggrid, 256, SMEM_H>>>(Xh, Wh + 0 * DD * DD, b1, Zh, -1, nullptr, nullptr);
    cudaStreamWaitEvent(0, ev_join, 0);   // agg needs CSR + dinv (+ W2/W3)

    agg_k<<<NN / 8, 256>>>(Zh, Ab, 0);
    gemm_k<1><<<ggrid, 256, SMEM_F>>>(Ab, Wh + 1 * DD * DD, b2, Zh, 0, g1, be1);
    agg_k<<<NN / 8, 256>>>(Zh, Ab, 1);
    gemm_k<1><<<ggrid, 256, SMEM_F>>>(Ab, Wh + 2 * DD * DD, b3, Zh, 1, g2, be2);
    agg_k<<<NN / 8, 256>>>(Zh, Ab, 2);

    apply_k<<<NN * DD / 4 / 256, 256>>>(Ab, out, g3, be3);
}

// round 13
// speedup vs baseline: 1.0450x; 1.0450x over previous
#include <cuda_runtime.h>
#include <cuda_fp16.h>
#include <cstdint>

#define NN 8192
#define EE 262144
#define DD 256
#define UMAX (EE + NN)
#define SLOT 128
#define BN_EPS 1e-5f

// GEMM tiling
#define BM 128
#define BNT 64
#define BK 32
#define ASH 40   // smem stride in halves

// ---------------- device scratch ----------------
__device__ unsigned g_bitmap[NN * (NN / 32)];
__device__ int      g_deg[NN];
__device__ int      g_nz;
__device__ int      g_colidx[NN * SLOT];
__device__ float    g_dinv[NN];
__device__ __half   g_Xh[NN * DD];
__device__ __half   g_Wh[3][DD * DD];
__device__ __half   g_Ah[NN * DD];
__device__ __half   g_Zh[NN * DD];
__device__ float    g_Abuf[NN * DD];
__device__ float    g_sum[3][DD];
__device__ float    g_sumsq[3][DD];

// ---------------- preprocessing ----------------
__global__ void detect_k(const unsigned* __restrict__ e) {
    int i = blockIdx.x * blockDim.x + threadIdx.x;
    if (i < 4096 && e[2 * i + 1] != 0u) atomicOr(&g_nz, 1);
}

__global__ void dedup_k(const void* __restrict__ eptr) {
    int i = blockIdx.x * blockDim.x + threadIdx.x;
    if (i >= UMAX) return;
    int is64 = (g_nz == 0);
    int r, c;
    if (i < EE) {
        if (is64) {
            const long long* e = (const long long*)eptr;
            r = (int)e[i];
            c = (int)e[EE + i];
        } else {
            const int* e = (const int*)eptr;
            r = e[i];
            c = e[EE + i];
        }
    } else {
        r = c = i - EE;   // self loop
    }
    unsigned bit = (unsigned)r * NN + (unsigned)c;
    unsigned mask = 1u << (bit & 31u);
    unsigned old = atomicOr(&g_bitmap[bit >> 5], mask);
    if (!(old & mask)) {
        int slot = atomicAdd(&g_deg[r], 1);
        if (slot < SLOT) g_colidx[r * SLOT + slot] = c;
    }
}

__global__ void dinv_k() {
    int i = blockIdx.x * blockDim.x + threadIdx.x;
    if (i < NN) g_dinv[i] = rsqrtf((float)g_deg[i]);
}

// ---------------- fp32 -> fp16 elementwise ----------------
__device__ __forceinline__ uint2 cvt4(float4 v) {
    __half2 lo = __floats2half2_rn(v.x, v.y);
    __half2 hi = __floats2half2_rn(v.z, v.w);
    uint2 u;
    u.x = *reinterpret_cast<unsigned*>(&lo);
    u.y = *reinterpret_cast<unsigned*>(&hi);
    return u;
}

__global__ void f2h_k(const float4* __restrict__ in, uint2* __restrict__ out, int n4) {
    int i = blockIdx.x * blockDim.x + threadIdx.x;
    if (i < n4) out[i] = cvt4(in[i]);
}

// two-segment convert: x then W1, one launch
__global__ void f2hx2_k(const float4* __restrict__ a, uint2* __restrict__ oa, int n4a,
                        const float4* __restrict__ b, uint2* __restrict__ ob, int n4b) {
    int i = blockIdx.x * blockDim.x + threadIdx.x;
    if (i < n4a) {
        oa[i] = cvt4(a[i]);
    } else {
        int j = i - n4a;
        if (j < n4b) ob[j] = cvt4(b[j]);
    }
}

// ---------------- BN + ReLU + cvt: Ah = fp16(relu(BN(Ab))) ----------------
__global__ __launch_bounds__(256) void bnrelu_k(const float* __restrict__ A,
                                                __half* __restrict__ Out, int layer,
                                                const float* __restrict__ gamma,
                                                const float* __restrict__ beta) {
    __shared__ float ssc[DD], ssh[DD];
    int tid = threadIdx.x;
    {
        float mu = g_sum[layer][tid] * (1.f / NN);
        float var = g_sumsq[layer][tid] * (1.f / NN) - mu * mu;
        float rs = rsqrtf(var + BN_EPS);
        float sc = gamma[tid] * rs;
        ssc[tid] = sc;
        ssh[tid] = beta[tid] - mu * sc;
    }
    __syncthreads();
    int i = blockIdx.x * 256 + tid;
    int col = (i * 4) & (DD - 1);
    float4 v = reinterpret_cast<const float4*>(A)[i];
    float a = fmaxf(fmaf(v.x, ssc[col],     ssh[col]),     0.f);
    float b = fmaxf(fmaf(v.y, ssc[col + 1], ssh[col + 1]), 0.f);
    float c = fmaxf(fmaf(v.z, ssc[col + 2], ssh[col + 2]), 0.f);
    float d = fmaxf(fmaf(v.w, ssc[col + 3], ssh[col + 3]), 0.f);
    __half2 lo = __floats2half2_rn(a, b);
    __half2 hi = __floats2half2_rn(c, d);
    uint2 u;
    u.x = *reinterpret_cast<unsigned*>(&lo);
    u.y = *reinterpret_cast<unsigned*>(&hi);
    reinterpret_cast<uint2*>(Out)[i] = u;
}

// ---------------- GEMM: Zh = A @ W^T + b  (fp16 HMMA m16n8k16, cp.async) ------
__device__ __forceinline__ void cpa16(void* dst, const void* src) {
    unsigned d = (unsigned)__cvta_generic_to_shared(dst);
    asm volatile("cp.async.ca.shared.global [%0], [%1], 16;\n" :: "r"(d), "l"(src));
}

__global__ __launch_bounds__(256, 2) void gemm_k(
    const __half* __restrict__ Ain, const __half* __restrict__ W,
    const float* __restrict__ bias, __half* __restrict__ Z)
{
    extern __shared__ __half sm[];
    __half* As = sm;                       // [2][BM][ASH]
    __half* Bs = sm + 2 * BM * ASH;        // [2][BNT][ASH]
#define AS(s,r,c) As[((s) * BM  + (r)) * ASH + (c)]
#define BS(s,r,c) Bs[((s) * BNT + (r)) * ASH + (c)]

    int tid = threadIdx.x;
    int bm = blockIdx.x * BM, bn = blockIdx.y * BNT;
    int wid = tid >> 5, lane = tid & 31;
    int g = lane >> 2, t = lane & 3;
    int wm = wid & 3, wn = wid >> 2;       // 4 x 2 warps, 32x32 per warp

    const __half* Abase = Ain + (size_t)bm * DD;
    const __half* Wbase = W + (size_t)bn * DD;

    float acc[2][4][4];
    #pragma unroll
    for (int mt = 0; mt < 2; mt++)
        #pragma unroll
        for (int nt = 0; nt < 4; nt++)
            #pragma unroll
            for (int q = 0; q < 4; q++) acc[mt][nt][q] = 0.f;

    {
        #pragma unroll
        for (int it = 0; it < 2; it++) {
            int f = tid + it * 256;
            int r = f >> 2, ch = (f & 3) * 8;
            cpa16(&AS(0, r, ch), Abase + r * DD + ch);
        }
        {
            int r = tid >> 2, ch = (tid & 3) * 8;
            cpa16(&BS(0, r, ch), Wbase + r * DD + ch);
        }
        asm volatile("cp.async.commit_group;");
    }
    __syncthreads();

    #pragma unroll 2
    for (int kb = 0; kb < DD / BK; kb++) {
        int s = kb & 1;
        if (kb < DD / BK - 1) {
            int kn = (kb + 1) * BK;
            #pragma unroll
            for (int it = 0; it < 2; it++) {
                int f = tid + it * 256;
                int r = f >> 2, ch = (f & 3) * 8;
                cpa16(&AS(s ^ 1, r, ch), Abase + r * DD + kn + ch);
            }
            {
                int r = tid >> 2, ch = (tid & 3) * 8;
                cpa16(&BS(s ^ 1, r, ch), Wbase + r * DD + kn + ch);
            }
            asm volatile("cp.async.commit_group;");
            asm volatile("cp.async.wait_group 1;");
        } else {
            asm volatile("cp.async.wait_group 0;");
        }
        __syncthreads();

        #pragma unroll
        for (int ks = 0; ks < 2; ks++) {
            int k16 = ks * 16;
            unsigned af[2][4], bf[4][2];
            #pragma unroll
            for (int mt = 0; mt < 2; mt++) {
                int rb = wm * 32 + mt * 16;
                af[mt][0] = *(const unsigned*)&AS(s, rb + g,     k16 + 2 * t);
                af[mt][1] = *(const unsigned*)&AS(s, rb + g + 8, k16 + 2 * t);
                af[mt][2] = *(const unsigned*)&AS(s, rb + g,     k16 + 2 * t + 8);
                af[mt][3] = *(const unsigned*)&AS(s, rb + g + 8, k16 + 2 * t + 8);
            }
            #pragma unroll
            for (int nt = 0; nt < 4; nt++) {
                int nb = wn * 32 + nt * 8;
                bf[nt][0] = *(const unsigned*)&BS(s, nb + g, k16 + 2 * t);
                bf[nt][1] = *(const unsigned*)&BS(s, nb + g, k16 + 2 * t + 8);
            }
            #pragma unroll
            for (int mt = 0; mt < 2; mt++)
                #pragma unroll
                for (int nt = 0; nt < 4; nt++) {
                    asm volatile(
                        "mma.sync.aligned.m16n8k16.row.col.f32.f16.f16.f32 "
                        "{%0,%1,%2,%3},{%4,%5,%6,%7},{%8,%9},{%0,%1,%2,%3};"
                        : "+f"(acc[mt][nt][0]), "+f"(acc[mt][nt][1]),
                          "+f"(acc[mt][nt][2]), "+f"(acc[mt][nt][3])
                        : "r"(af[mt][0]), "r"(af[mt][1]), "r"(af[mt][2]), "r"(af[mt][3]),
                          "r"(bf[nt][0]), "r"(bf[nt][1]));
                }
        }
        __syncthreads();
    }

    #pragma unroll
    for (int mt = 0; mt < 2; mt++)
        #pragma unroll
        for (int nt = 0; nt < 4; nt++) {
            int r0 = bm + wm * 32 + mt * 16 + g;
            int col = bn + wn * 32 + nt * 8 + 2 * t;
            float b0 = bias[col], b1 = bias[col + 1];
            __half2 p0 = __floats2half2_rn(acc[mt][nt][0] + b0, acc[mt][nt][1] + b1);
            __half2 p1 = __floats2half2_rn(acc[mt][nt][2] + b0, acc[mt][nt][3] + b1);
            *reinterpret_cast<__half2*>(Z + (size_t)r0 * DD + col)       = p0;
            *reinterpret_cast<__half2*>(Z + (size_t)(r0 + 8) * DD + col) = p1;
        }
#undef AS
#undef BS
}

// ---------------- sparse aggregation (fp16 Z) + fused BN stats ----------------
// 1 warp per row, uint4 per lane; neighbor batch of 8 for deeper MLP.
__global__ __launch_bounds__(256) void agg_k(const __half* __restrict__ Z,
                                             float* __restrict__ Out, int layer) {
    __shared__ float sv[8][DD];
    int tid = threadIdx.x;
    int w = tid >> 5;
    int row = blockIdx.x * 8 + w;
    int lane = tid & 31;

    int deg = g_deg[row];
    const int* cols = &g_colidx[row * SLOT];
    float a[8];
    #pragma unroll
    for (int j = 0; j < 8; j++) a[j] = 0.f;

    int p = 0;
    for (; p + 8 <= deg; p += 8) {
        int cc[8];
        #pragma unroll
        for (int q = 0; q < 8; q++) cc[q] = cols[p + q];
        float dv[8];
        uint4 u[8];
        #pragma unroll
        for (int q = 0; q < 8; q++) {
            dv[q] = g_dinv[cc[q]];
            u[q] = __ldg((const uint4*)(Z + (size_t)cc[q] * DD) + lane);
        }
        #pragma unroll
        for (int q = 0; q < 8; q++) {
            float2 f0 = __half22float2(*reinterpret_cast<__half2*>(&u[q].x));
            float2 f1 = __half22float2(*reinterpret_cast<__half2*>(&u[q].y));
            float2 f2 = __half22float2(*reinterpret_cast<__half2*>(&u[q].z));
            float2 f3 = __half22float2(*reinterpret_cast<__half2*>(&u[q].w));
            a[0] = fmaf(dv[q], f0.x, a[0]); a[1] = fmaf(dv[q], f0.y, a[1]);
            a[2] = fmaf(dv[q], f1.x, a[2]); a[3] = fmaf(dv[q], f1.y, a[3]);
            a[4] = fmaf(dv[q], f2.x, a[4]); a[5] = fmaf(dv[q], f2.y, a[5]);
            a[6] = fmaf(dv[q], f3.x, a[6]); a[7] = fmaf(dv[q], f3.y, a[7]);
        }
    }
    for (; p < deg; p++) {
        int c = cols[p];
        float dv = g_dinv[c];
        uint4 u = __ldg((const uint4*)(Z + (size_t)c * DD) + lane);
        float2 f0 = __half22float2(*reinterpret_cast<__half2*>(&u.x));
        float2 f1 = __half22float2(*reinterpret_cast<__half2*>(&u.y));
        float2 f2 = __half22float2(*reinterpret_cast<__half2*>(&u.z));
        float2 f3 = __half22float2(*reinterpret_cast<__half2*>(&u.w));
        a[0] = fmaf(dv, f0.x, a[0]); a[1] = fmaf(dv, f0.y, a[1]);
        a[2] = fmaf(dv, f1.x, a[2]); a[3] = fmaf(dv, f1.y, a[3]);
        a[4] = fmaf(dv, f2.x, a[4]); a[5] = fmaf(dv, f2.y, a[5]);
        a[6] = fmaf(dv, f3.x, a[6]); a[7] = fmaf(dv, f3.y, a[7]);
    }
    float dr = g_dinv[row];
    #pragma unroll
    for (int j = 0; j < 8; j++) a[j] *= dr;

    float4* orow = reinterpret_cast<float4*>(Out + (size_t)row * DD);
    orow[lane * 2]     = make_float4(a[0], a[1], a[2], a[3]);
    orow[lane * 2 + 1] = make_float4(a[4], a[5], a[6], a[7]);

    #pragma unroll
    for (int j = 0; j < 8; j++) sv[w][lane * 8 + j] = a[j];
    __syncthreads();
    float s = 0.f, ss = 0.f;
    #pragma unroll
    for (int r = 0; r < 8; r++) {
        float v = sv[r][tid];
        s += v;
        ss = fmaf(v, v, ss);
    }
    atomicAdd(&g_sum[layer][tid], s);
    atomicAdd(&g_sumsq[layer][tid], ss);
}

// final BN apply (fp32 out, no relu)
__global__ __launch_bounds__(256) void apply_k(const float* __restrict__ A,
                                               float* __restrict__ out,
                                               const float* __restrict__ gamma,
                                               const float* __restrict__ beta) {
    __shared__ float ssc[DD], ssh[DD];
    int tid = threadIdx.x;
    {
        float mu = g_sum[2][tid] * (1.f / NN);
        float var = g_sumsq[2][tid] * (1.f / NN) - mu * mu;
        float rs = rsqrtf(var + BN_EPS);
        float sc = gamma[tid] * rs;
        ssc[tid] = sc;
        ssh[tid] = beta[tid] - mu * sc;
    }
    __syncthreads();
    int i = blockIdx.x * 256 + tid;
    int col = (i * 4) & (DD - 1);
    float4 v = reinterpret_cast<const float4*>(A)[i];
    float4 o;
    o.x = fmaf(v.x, ssc[col],     ssh[col]);
    o.y = fmaf(v.y, ssc[col + 1], ssh[col + 1]);
    o.z = fmaf(v.z, ssc[col + 2], ssh[col + 2]);
    o.w = fmaf(v.w, ssc[col + 3], ssh[col + 3]);
    reinterpret_cast<float4*>(out)[i] = o;
}

// ---------------- launch ----------------
extern "C" void kernel_launch(void* const* d_in, const int* in_sizes, int n_in,
                              void* d_out, int out_size) {
    const float* x   = (const float*)d_in[0];
    const void*  ei  = d_in[1];
    const float* W1  = (const float*)d_in[2];
    const float* b1  = (const float*)d_in[3];
    const float* W2  = (const float*)d_in[4];
    const float* b2  = (const float*)d_in[5];
    const float* W3  = (const float*)d_in[6];
    const float* b3  = (const float*)d_in[7];
    const float* g1  = (const float*)d_in[8];
    const float* be1 = (const float*)d_in[9];
    const float* g2  = (const float*)d_in[10];
    const float* be2 = (const float*)d_in[11];
    const float* g3  = (const float*)d_in[12];
    const float* be3 = (const float*)d_in[13];
    float* out = (float*)d_out;

    void *pZ, *pA, *pBm, *pDeg, *pSum, *pSq, *pNz, *pXh, *pWh, *pAh;
    cudaGetSymbolAddress(&pZ, g_Zh);
    cudaGetSymbolAddress(&pA, g_Abuf);
    cudaGetSymbolAddress(&pBm, g_bitmap);
    cudaGetSymbolAddress(&pDeg, g_deg);
    cudaGetSymbolAddress(&pSum, g_sum);
    cudaGetSymbolAddress(&pSq, g_sumsq);
    cudaGetSymbolAddress(&pNz, g_nz);
    cudaGetSymbolAddress(&pXh, g_Xh);
    cudaGetSymbolAddress(&pWh, g_Wh);
    cudaGetSymbolAddress(&pAh, g_Ah);
    __half* Zh = (__half*)pZ;
    float*  Ab = (float*)pA;
    __half* Xh = (__half*)pXh;
    __half* Wh = (__half*)pWh;
    __half* Ah = (__half*)pAh;

    const int GEMM_SMEM = (2 * BM * ASH + 2 * BNT * ASH) * 2;
    cudaFuncSetAttribute(gemm_k, cudaFuncAttributeMaxDynamicSharedMemorySize, GEMM_SMEM);

    static cudaStream_t s_pre = nullptr;
    static cudaEvent_t ev_fork = nullptr, ev_join = nullptr;
    if (s_pre == nullptr) {
        cudaStreamCreateWithFlags(&s_pre, cudaStreamNonBlocking);
        cudaEventCreateWithFlags(&ev_fork, cudaEventDisableTiming);
        cudaEventCreateWithFlags(&ev_join, cudaEventDisableTiming);
    }

    cudaMemsetAsync(pSum, 0, sizeof(float) * 3 * DD);
    cudaMemsetAsync(pSq, 0, sizeof(float) * 3 * DD);

    // ---- fork: preprocessing + W2/W3 converts, concurrent with x/W1 + gemm1
    cudaEventRecord(ev_fork, 0);
    cudaStreamWaitEvent(s_pre, ev_fork, 0);
    cudaMemsetAsync(pBm, 0, sizeof(unsigned) * NN * (NN / 32), s_pre);
    cudaMemsetAsync(pDeg, 0, sizeof(int) * NN, s_pre);
    cudaMemsetAsync(pNz, 0, sizeof(int), s_pre);
    detect_k<<<16, 256, 0, s_pre>>>((const unsigned*)ei);
    dedup_k<<<(UMAX + 255) / 256, 256, 0, s_pre>>>(ei);
    dinv_k<<<NN / 256, 256, 0, s_pre>>>();
    f2h_k<<<(DD * DD / 4 + 255) / 256, 256, 0, s_pre>>>(
        (const float4*)W2, (uint2*)(Wh + 1 * DD * DD), DD * DD / 4);
    f2h_k<<<(DD * DD / 4 + 255) / 256, 256, 0, s_pre>>>(
        (const float4*)W3, (uint2*)(Wh + 2 * DD * DD), DD * DD / 4);
    cudaEventRecord(ev_join, s_pre);

    // main: x + W1 convert (single launch)
    f2hx2_k<<<(NN * DD / 4 + DD * DD / 4 + 255) / 256, 256>>>(
        (const float4*)x, (uint2*)Xh, NN * DD / 4,
        (const float4*)W1, (uint2*)(Wh + 0 * DD * DD), DD * DD / 4);

    dim3 ggrid(NN / BM, DD / BNT);

    // layer 1 — concurrent with preprocessing fork
    gemm_k<<<ggrid, 256, GEMM_SMEM>>>(Xh, Wh + 0 * DD * DD, b1, Zh);
    cudaStreamWaitEvent(0, ev_join, 0);   // agg needs CSR + dinv

    agg_k<<<NN / 8, 256>>>(Zh, Ab, 0);
    bnrelu_k<<<NN * DD / 4 / 256, 256>>>(Ab, Ah, 0, g1, be1);
    gemm_k<<<ggrid, 256, GEMM_SMEM>>>(Ah, Wh + 1 * DD * DD, b2, Zh);
    agg_k<<<NN / 8, 256>>>(Zh, Ab, 1);
    bnrelu_k<<<NN * DD / 4 / 256, 256>>>(Ab, Ah, 1, g2, be2);
    gemm_k<<<ggrid, 256, GEMM_SMEM>>>(Ah, Wh + 2 * DD * DD, b3, Zh);
    agg_k<<<NN / 8, 256>>>(Zh, Ab, 2);

    apply_k<<<NN * DD / 4 / 256, 256>>>(Ab, out, g3, be3);
}

// round 14
// speedup vs baseline: 1.0581x; 1.0125x over previous
#include <cuda_runtime.h>
#include <cuda_fp16.h>
#include <cstdint>

#define NN 8192
#define EE 262144
#define DD 256
#define UMAX (EE + NN)
#define SLOT 128
#define BN_EPS 1e-5f

// GEMM tiling
#define BM 128
#define BNT 64
#define BK 32
#define ASH 40      // smem stride in halves
#define NSTAGE 3
#define NT (DD / BK)   // 8 K-tiles

// ---------------- device scratch ----------------
__device__ unsigned g_bitmap[NN * (NN / 32)];
__device__ int      g_deg[NN];
__device__ int      g_nz;
__device__ int      g_colidx[NN * SLOT];
__device__ float    g_dinv[NN];
__device__ __half   g_Xh[NN * DD];
__device__ __half   g_Wh[3][DD * DD];
__device__ __half   g_Ah[NN * DD];
__device__ __half   g_Zh[NN * DD];
__device__ float    g_Abuf[NN * DD];
__device__ float    g_sum[3][DD];
__device__ float    g_sumsq[3][DD];

// ---------------- preprocessing ----------------
__global__ void detect_k(const unsigned* __restrict__ e) {
    int i = blockIdx.x * blockDim.x + threadIdx.x;
    if (i < 4096 && e[2 * i + 1] != 0u) atomicOr(&g_nz, 1);
}

__global__ void dedup_k(const void* __restrict__ eptr) {
    int i = blockIdx.x * blockDim.x + threadIdx.x;
    if (i >= UMAX) return;
    int is64 = (g_nz == 0);
    int r, c;
    if (i < EE) {
        if (is64) {
            const long long* e = (const long long*)eptr;
            r = (int)e[i];
            c = (int)e[EE + i];
        } else {
            const int* e = (const int*)eptr;
            r = e[i];
            c = e[EE + i];
        }
    } else {
        r = c = i - EE;   // self loop
    }
    unsigned bit = (unsigned)r * NN + (unsigned)c;
    unsigned mask = 1u << (bit & 31u);
    unsigned old = atomicOr(&g_bitmap[bit >> 5], mask);
    if (!(old & mask)) {
        int slot = atomicAdd(&g_deg[r], 1);
        if (slot < SLOT) g_colidx[r * SLOT + slot] = c;
    }
}

__global__ void dinv_k() {
    int i = blockIdx.x * blockDim.x + threadIdx.x;
    if (i < NN) g_dinv[i] = rsqrtf((float)g_deg[i]);
}

// ---------------- fp32 -> fp16 elementwise ----------------
__device__ __forceinline__ uint2 cvt4(float4 v) {
    __half2 lo = __floats2half2_rn(v.x, v.y);
    __half2 hi = __floats2half2_rn(v.z, v.w);
    uint2 u;
    u.x = *reinterpret_cast<unsigned*>(&lo);
    u.y = *reinterpret_cast<unsigned*>(&hi);
    return u;
}

__global__ void f2h_k(const float4* __restrict__ in, uint2* __restrict__ out, int n4) {
    int i = blockIdx.x * blockDim.x + threadIdx.x;
    if (i < n4) out[i] = cvt4(in[i]);
}

__global__ void f2hx2_k(const float4* __restrict__ a, uint2* __restrict__ oa, int n4a,
                        const float4* __restrict__ b, uint2* __restrict__ ob, int n4b) {
    int i = blockIdx.x * blockDim.x + threadIdx.x;
    if (i < n4a) {
        oa[i] = cvt4(a[i]);
    } else {
        int j = i - n4a;
        if (j < n4b) ob[j] = cvt4(b[j]);
    }
}

// ---------------- BN + ReLU + cvt: Ah = fp16(relu(BN(Ab))) ----------------
__global__ __launch_bounds__(256) void bnrelu_k(const float* __restrict__ A,
                                                __half* __restrict__ Out, int layer,
                                                const float* __restrict__ gamma,
                                                const float* __restrict__ beta) {
    __shared__ float ssc[DD], ssh[DD];
    int tid = threadIdx.x;
    {
        float mu = g_sum[layer][tid] * (1.f / NN);
        float var = g_sumsq[layer][tid] * (1.f / NN) - mu * mu;
        float rs = rsqrtf(var + BN_EPS);
        float sc = gamma[tid] * rs;
        ssc[tid] = sc;
        ssh[tid] = beta[tid] - mu * sc;
    }
    __syncthreads();
    int i = blockIdx.x * 256 + tid;
    int col = (i * 4) & (DD - 1);
    float4 v = reinterpret_cast<const float4*>(A)[i];
    float a = fmaxf(fmaf(v.x, ssc[col],     ssh[col]),     0.f);
    float b = fmaxf(fmaf(v.y, ssc[col + 1], ssh[col + 1]), 0.f);
    float c = fmaxf(fmaf(v.z, ssc[col + 2], ssh[col + 2]), 0.f);
    float d = fmaxf(fmaf(v.w, ssc[col + 3], ssh[col + 3]), 0.f);
    __half2 lo = __floats2half2_rn(a, b);
    __half2 hi = __floats2half2_rn(c, d);
    uint2 u;
    u.x = *reinterpret_cast<unsigned*>(&lo);
    u.y = *reinterpret_cast<unsigned*>(&hi);
    reinterpret_cast<uint2*>(Out)[i] = u;
}

// ---------------- GEMM: Zh = A @ W^T + b  (fp16 HMMA, 3-stage cp.async) ------
__device__ __forceinline__ void cpa16(void* dst, const void* src) {
    unsigned d = (unsigned)__cvta_generic_to_shared(dst);
    asm volatile("cp.async.ca.shared.global [%0], [%1], 16;\n" :: "r"(d), "l"(src));
}

__global__ __launch_bounds__(256, 2) void gemm_k(
    const __half* __restrict__ Ain, const __half* __restrict__ W,
    const float* __restrict__ bias, __half* __restrict__ Z)
{
    extern __shared__ __half sm[];
    __half* As = sm;                          // [NSTAGE][BM][ASH]
    __half* Bs = sm + NSTAGE * BM * ASH;      // [NSTAGE][BNT][ASH]
#define AS(s,r,c) As[((s) * BM  + (r)) * ASH + (c)]
#define BS(s,r,c) Bs[((s) * BNT + (r)) * ASH + (c)]

    int tid = threadIdx.x;
    int bm = blockIdx.x * BM, bn = blockIdx.y * BNT;
    int wid = tid >> 5, lane = tid & 31;
    int g = lane >> 2, t = lane & 3;
    int wm = wid & 3, wn = wid >> 2;          // 4 x 2 warps, 32x32 per warp

    const __half* Abase = Ain + (size_t)bm * DD;
    const __half* Wbase = W + (size_t)bn * DD;

    // fill indices (constant per thread)
    int fa0_r = tid >> 2,          fa0_c = (tid & 3) * 8;
    int fa1_r = (tid + 256) >> 2,  fa1_c = (tid & 3) * 8;
    int fb_r  = tid >> 2,          fb_c  = (tid & 3) * 8;

    float acc[2][4][4];
    #pragma unroll
    for (int mt = 0; mt < 2; mt++)
        #pragma unroll
        for (int nt = 0; nt < 4; nt++)
            #pragma unroll
            for (int q = 0; q < 4; q++) acc[mt][nt][q] = 0.f;

    // prologue: issue stages 0 and 1
    #pragma unroll
    for (int pk = 0; pk < 2; pk++) {
        int ko = pk * BK;
        cpa16(&AS(pk, fa0_r, fa0_c), Abase + fa0_r * DD + ko + fa0_c);
        cpa16(&AS(pk, fa1_r, fa1_c), Abase + fa1_r * DD + ko + fa1_c);
        cpa16(&BS(pk, fb_r, fb_c),  Wbase + fb_r * DD + ko + fb_c);
        asm volatile("cp.async.commit_group;");
    }

    #pragma unroll
    for (int kb = 0; kb < NT; kb++) {
        int s = kb % NSTAGE;
        if (kb + 2 < NT) {
            int sp = (kb + 2) % NSTAGE;
            int ko = (kb + 2) * BK;
            cpa16(&AS(sp, fa0_r, fa0_c), Abase + fa0_r * DD + ko + fa0_c);
            cpa16(&AS(sp, fa1_r, fa1_c), Abase + fa1_r * DD + ko + fa1_c);
            cpa16(&BS(sp, fb_r, fb_c),  Wbase + fb_r * DD + ko + fb_c);
            asm volatile("cp.async.commit_group;");
            asm volatile("cp.async.wait_group 2;");
        } else if (kb + 1 < NT) {
            asm volatile("cp.async.wait_group 1;");
        } else {
            asm volatile("cp.async.wait_group 0;");
        }
        __syncthreads();

        #pragma unroll
        for (int ks = 0; ks < 2; ks++) {
            int k16 = ks * 16;
            unsigned af[2][4], bf[4][2];
            #pragma unroll
            for (int mt = 0; mt < 2; mt++) {
                int rb = wm * 32 + mt * 16;
                af[mt][0] = *(const unsigned*)&AS(s, rb + g,     k16 + 2 * t);
                af[mt][1] = *(const unsigned*)&AS(s, rb + g + 8, k16 + 2 * t);
                af[mt][2] = *(const unsigned*)&AS(s, rb + g,     k16 + 2 * t + 8);
                af[mt][3] = *(const unsigned*)&AS(s, rb + g + 8, k16 + 2 * t + 8);
            }
            #pragma unroll
            for (int nt = 0; nt < 4; nt++) {
                int nb = wn * 32 + nt * 8;
                bf[nt][0] = *(const unsigned*)&BS(s, nb + g, k16 + 2 * t);
                bf[nt][1] = *(const unsigned*)&BS(s, nb + g, k16 + 2 * t + 8);
            }
            #pragma unroll
            for (int mt = 0; mt < 2; mt++)
                #pragma unroll
                for (int nt = 0; nt < 4; nt++) {
                    asm volatile(
                        "mma.sync.aligned.m16n8k16.row.col.f32.f16.f16.f32 "
                        "{%0,%1,%2,%3},{%4,%5,%6,%7},{%8,%9},{%0,%1,%2,%3};"
                        : "+f"(acc[mt][nt][0]), "+f"(acc[mt][nt][1]),
                          "+f"(acc[mt][nt][2]), "+f"(acc[mt][nt][3])
                        : "r"(af[mt][0]), "r"(af[mt][1]), "r"(af[mt][2]), "r"(af[mt][3]),
                          "r"(bf[nt][0]), "r"(bf[nt][1]));
                }
        }
        __syncthreads();
    }

    #pragma unroll
    for (int mt = 0; mt < 2; mt++)
        #pragma unroll
        for (int nt = 0; nt < 4; nt++) {
            int r0 = bm + wm * 32 + mt * 16 + g;
            int col = bn + wn * 32 + nt * 8 + 2 * t;
            float b0 = bias[col], b1 = bias[col + 1];
            __half2 p0 = __floats2half2_rn(acc[mt][nt][0] + b0, acc[mt][nt][1] + b1);
            __half2 p1 = __floats2half2_rn(acc[mt][nt][2] + b0, acc[mt][nt][3] + b1);
            *reinterpret_cast<__half2*>(Z + (size_t)r0 * DD + col)       = p0;
            *reinterpret_cast<__half2*>(Z + (size_t)(r0 + 8) * DD + col) = p1;
        }
#undef AS
#undef BS
}

// ---------------- sparse aggregation (fp16 Z) + fused BN stats ----------------
// 1 warp per row, uint4 per lane (full 512B row per warp per neighbor), batch 4.
__global__ __launch_bounds__(256) void agg_k(const __half* __restrict__ Z,
                                             float* __restrict__ Out, int layer) {
    __shared__ float sv[8][DD];
    int tid = threadIdx.x;
    int w = tid >> 5;
    int row = blockIdx.x * 8 + w;
    int lane = tid & 31;

    int deg = g_deg[row];
    const int* cols = &g_colidx[row * SLOT];
    float a[8];
    #pragma unroll
    for (int j = 0; j < 8; j++) a[j] = 0.f;

    int p = 0;
    for (; p + 4 <= deg; p += 4) {
        int cc[4];
        #pragma unroll
        for (int q = 0; q < 4; q++) cc[q] = cols[p + q];
        float dv[4];
        uint4 u[4];
        #pragma unroll
        for (int q = 0; q < 4; q++) {
            dv[q] = g_dinv[cc[q]];
            u[q] = __ldg((const uint4*)(Z + (size_t)cc[q] * DD) + lane);
        }
        #pragma unroll
        for (int q = 0; q < 4; q++) {
            float2 f0 = __half22float2(*reinterpret_cast<__half2*>(&u[q].x));
            float2 f1 = __half22float2(*reinterpret_cast<__half2*>(&u[q].y));
            float2 f2 = __half22float2(*reinterpret_cast<__half2*>(&u[q].z));
            float2 f3 = __half22float2(*reinterpret_cast<__half2*>(&u[q].w));
            a[0] = fmaf(dv[q], f0.x, a[0]); a[1] = fmaf(dv[q], f0.y, a[1]);
            a[2] = fmaf(dv[q], f1.x, a[2]); a[3] = fmaf(dv[q], f1.y, a[3]);
            a[4] = fmaf(dv[q], f2.x, a[4]); a[5] = fmaf(dv[q], f2.y, a[5]);
            a[6] = fmaf(dv[q], f3.x, a[6]); a[7] = fmaf(dv[q], f3.y, a[7]);
        }
    }
    for (; p < deg; p++) {
        int c = cols[p];
        float dv = g_dinv[c];
        uint4 u = __ldg((const uint4*)(Z + (size_t)c * DD) + lane);
        float2 f0 = __half22float2(*reinterpret_cast<__half2*>(&u.x));
        float2 f1 = __half22float2(*reinterpret_cast<__half2*>(&u.y));
        float2 f2 = __half22float2(*reinterpret_cast<__half2*>(&u.z));
        float2 f3 = __half22float2(*reinterpret_cast<__half2*>(&u.w));
        a[0] = fmaf(dv, f0.x, a[0]); a[1] = fmaf(dv, f0.y, a[1]);
        a[2] = fmaf(dv, f1.x, a[2]); a[3] = fmaf(dv, f1.y, a[3]);
        a[4] = fmaf(dv, f2.x, a[4]); a[5] = fmaf(dv, f2.y, a[5]);
        a[6] = fmaf(dv, f3.x, a[6]); a[7] = fmaf(dv, f3.y, a[7]);
    }
    float dr = g_dinv[row];
    #pragma unroll
    for (int j = 0; j < 8; j++) a[j] *= dr;

    float4* orow = reinterpret_cast<float4*>(Out + (size_t)row * DD);
    orow[lane * 2]     = make_float4(a[0], a[1], a[2], a[3]);
    orow[lane * 2 + 1] = make_float4(a[4], a[5], a[6], a[7]);

    #pragma unroll
    for (int j = 0; j < 8; j++) sv[w][lane * 8 + j] = a[j];
    __syncthreads();
    float s = 0.f, ss = 0.f;
    #pragma unroll
    for (int r = 0; r < 8; r++) {
        float v = sv[r][tid];
        s += v;
        ss = fmaf(v, v, ss);
    }
    atomicAdd(&g_sum[layer][tid], s);
    atomicAdd(&g_sumsq[layer][tid], ss);
}

// final BN apply (fp32 out, no relu)
__global__ __launch_bounds__(256) void apply_k(const float* __restrict__ A,
                                               float* __restrict__ out,
                                               const float* __restrict__ gamma,
                                               const float* __restrict__ beta) {
    __shared__ float ssc[DD], ssh[DD];
    int tid = threadIdx.x;
    {
        float mu = g_sum[2][tid] * (1.f / NN);
        float var = g_sumsq[2][tid] * (1.f / NN) - mu * mu;
        float rs = rsqrtf(var + BN_EPS);
        float sc = gamma[tid] * rs;
        ssc[tid] = sc;
        ssh[tid] = beta[tid] - mu * sc;
    }
    __syncthreads();
    int i = blockIdx.x * 256 + tid;
    int col = (i * 4) & (DD - 1);
    float4 v = reinterpret_cast<const float4*>(A)[i];
    float4 o;
    o.x = fmaf(v.x, ssc[col],     ssh[col]);
    o.y = fmaf(v.y, ssc[col + 1], ssh[col + 1]);
    o.z = fmaf(v.z, ssc[col + 2], ssh[col + 2]);
    o.w = fmaf(v.w, ssc[col + 3], ssh[col + 3]);
    reinterpret_cast<float4*>(out)[i] = o;
}

// ---------------- launch ----------------
extern "C" void kernel_launch(void* const* d_in, const int* in_sizes, int n_in,
                              void* d_out, int out_size) {
    const float* x   = (const float*)d_in[0];
    const void*  ei  = d_in[1];
    const float* W1  = (const float*)d_in[2];
    const float* b1  = (const float*)d_in[3];
    const float* W2  = (const float*)d_in[4];
    const float* b2  = (const float*)d_in[5];
    const float* W3  = (const float*)d_in[6];
    const float* b3  = (const float*)d_in[7];
    const float* g1  = (const float*)d_in[8];
    const float* be1 = (const float*)d_in[9];
    const float* g2  = (const float*)d_in[10];
    const float* be2 = (const float*)d_in[11];
    const float* g3  = (const float*)d_in[12];
    const float* be3 = (const float*)d_in[13];
    float* out = (float*)d_out;

    void *pZ, *pA, *pBm, *pDeg, *pSum, *pSq, *pNz, *pXh, *pWh, *pAh;
    cudaGetSymbolAddress(&pZ, g_Zh);
    cudaGetSymbolAddress(&pA, g_Abuf);
    cudaGetSymbolAddress(&pBm, g_bitmap);
    cudaGetSymbolAddress(&pDeg, g_deg);
    cudaGetSymbolAddress(&pSum, g_sum);
    cudaGetSymbolAddress(&pSq, g_sumsq);
    cudaGetSymbolAddress(&pNz, g_nz);
    cudaGetSymbolAddress(&pXh, g_Xh);
    cudaGetSymbolAddress(&pWh, g_Wh);
    cudaGetSymbolAddress(&pAh, g_Ah);
    __half* Zh = (__half*)pZ;
    float*  Ab = (float*)pA;
    __half* Xh = (__half*)pXh;
    __half* Wh = (__half*)pWh;
    __half* Ah = (__half*)pAh;

    const int GEMM_SMEM = NSTAGE * (BM * ASH + BNT * ASH) * 2;   // bytes
    cudaFuncSetAttribute(gemm_k, cudaFuncAttributeMaxDynamicSharedMemorySize, GEMM_SMEM);

    static cudaStream_t s_pre = nullptr;
    static cudaEvent_t ev_fork = nullptr, ev_join = nullptr;
    if (s_pre == nullptr) {
        cudaStreamCreateWithFlags(&s_pre, cudaStreamNonBlocking);
        cudaEventCreateWithFlags(&ev_fork, cudaEventDisableTiming);
        cudaEventCreateWithFlags(&ev_join, cudaEventDisableTiming);
    }

    cudaMemsetAsync(pSum, 0, sizeof(float) * 3 * DD);
    cudaMemsetAsync(pSq, 0, sizeof(float) * 3 * DD);

    // ---- fork: preprocessing + W2/W3 converts, concurrent with x/W1 + gemm1
    cudaEventRecord(ev_fork, 0);
    cudaStreamWaitEvent(s_pre, ev_fork, 0);
    cudaMemsetAsync(pBm, 0, sizeof(unsigned) * NN * (NN / 32), s_pre);
    cudaMemsetAsync(pDeg, 0, sizeof(int) * NN, s_pre);
    cudaMemsetAsync(pNz, 0, sizeof(int), s_pre);
    detect_k<<<16, 256, 0, s_pre>>>((const unsigned*)ei);
    dedup_k<<<(UMAX + 255) / 256, 256, 0, s_pre>>>(ei);
    dinv_k<<<NN / 256, 256, 0, s_pre>>>();
    f2h_k<<<(DD * DD / 4 + 255) / 256, 256, 0, s_pre>>>(
        (const float4*)W2, (uint2*)(Wh + 1 * DD * DD), DD * DD / 4);
    f2h_k<<<(DD * DD / 4 + 255) / 256, 256, 0, s_pre>>>(
        (const float4*)W3, (uint2*)(Wh + 2 * DD * DD), DD * DD / 4);
    cudaEventRecord(ev_join, s_pre);

    // main: x + W1 convert (single launch)
    f2hx2_k<<<(NN * DD / 4 + DD * DD / 4 + 255) / 256, 256>>>(
        (const float4*)x, (uint2*)Xh, NN * DD / 4,
        (const float4*)W1, (uint2*)(Wh + 0 * DD * DD), DD * DD / 4);

    dim3 ggrid(NN / BM, DD / BNT);

    // layer 1 — concurrent with preprocessing fork
    gemm_k<<<ggrid, 256, GEMM_SMEM>>>(Xh, Wh + 0 * DD * DD, b1, Zh);
    cudaStreamWaitEvent(0, ev_join, 0);   // agg needs CSR + dinv

    agg_k<<<NN / 8, 256>>>(Zh, Ab, 0);
    bnrelu_k<<<NN * DD / 4 / 256, 256>>>(Ab, Ah, 0, g1, be1);
    gemm_k<<<ggrid, 256, GEMM_SMEM>>>(Ah, Wh + 1 * DD * DD, b2, Zh);
    agg_k<<<NN / 8, 256>>>(Zh, Ab, 1);
    bnrelu_k<<<NN * DD / 4 / 256, 256>>>(Ab, Ah, 1, g2, be2);
    gemm_k<<<ggrid, 256, GEMM_SMEM>>>(Ah, Wh + 2 * DD * DD, b3, Zh);
    agg_k<<<NN / 8, 256>>>(Zh, Ab, 2);

    apply_k<<<NN * DD / 4 / 256, 256>>>(Ab, out, g3, be3);
}